// round 14
// baseline (speedup 1.0000x reference)
#include <cuda_runtime.h>

typedef unsigned long long u64;
typedef unsigned int u32;

#define CAP 2097152
#define EPSBN 1e-5f
#define SGRID 1184
#define TB 256

__device__ float4 g_h2[4 * CAP];                    // h2 plane-major: [plane p][row]
__device__ float g_stats[5][32];                    // [stage][sum 0..15 | sumsq 0..15]
__device__ __align__(16) float g_ctab[8 * 64];      // emb@wc_tail^T + bc

// ---------------- packed helpers (k_final phase B only) ----------------
__device__ __forceinline__ u64 pack2(float x, float y) {
  u64 d;
  asm("mov.b64 %0, {%1, %2};" : "=l"(d) : "r"(__float_as_uint(x)), "r"(__float_as_uint(y)));
  return d;
}
__device__ __forceinline__ void unpack2(u64 a, float& x, float& y) {
  u32 lo, hi;
  asm("mov.b64 {%0, %1}, %2;" : "=r"(lo), "=r"(hi) : "l"(a));
  x = __uint_as_float(lo); y = __uint_as_float(hi);
}
__device__ __forceinline__ u64 fma2(u64 a, u64 b, u64 c) {
  u64 d;
  asm("fma.rn.f32x2 %0, %1, %2, %3;" : "=l"(d) : "l"(a), "l"(b), "l"(c));
  return d;
}
__device__ __forceinline__ u64 ldu64(const float2* p) {
  return *reinterpret_cast<const u64*>(p);
}

// ---------------- BN folding (scalar smem layouts) ----------------
// wq[j*4+q] = float4 of W'[4q..4q+3][j]; fb4[q] = float4 of b'[4q..4q+3]
__device__ void fold_bn_layer16(int stage, float invN,
                                const float* bng, const float* bnb,
                                const float* w, const float* bias,
                                float* ss, float4* wq, float4* fb4) {
  int t = threadIdx.x;
  if (t < 16) {
    float m = g_stats[stage][t] * invN;
    float var = fmaf(-m, m, g_stats[stage][16 + t] * invN);
    float scale = rsqrtf(var + EPSBN) * bng[t];
    ss[t] = scale;
    ss[16 + t] = bnb[t] - m * scale;
  }
  __syncthreads();
  if (t < 64) {
    int j = t >> 2, q = t & 3;
    float s = ss[j];
    wq[j * 4 + q] = make_float4(w[(4 * q) * 16 + j] * s, w[(4 * q + 1) * 16 + j] * s,
                                w[(4 * q + 2) * 16 + j] * s, w[(4 * q + 3) * 16 + j] * s);
  }
  if (t >= 64 && t < 80) {
    int o = t - 64;
    float a = bias[o];
#pragma unroll
    for (int j = 0; j < 16; j++) a = fmaf(w[o * 16 + j], ss[16 + j], a);
    ((float*)fb4)[o] = a;
  }
}

// layer1: w1A4/w1B4[4] = per-column folded weights, fb14[4] = folded bias
__device__ void fold_bn_layer1(float invN,
                               const float* bng, const float* bnb,
                               const float* w1, const float* b1,
                               float* ss, float4* w1A4, float4* w1B4, float4* fb14) {
  int t = threadIdx.x;
  if (t < 2) {
    float m = g_stats[0][t] * invN;
    float var = fmaf(-m, m, g_stats[0][16 + t] * invN);
    float scale = rsqrtf(var + EPSBN) * bng[t];
    ss[t] = scale;
    ss[2 + t] = bnb[t] - m * scale;
  }
  __syncthreads();
  if (t >= 128 && t < 144) {
    int o = t - 128;
    ((float*)w1A4)[o] = w1[o * 2 + 0] * ss[0];
    ((float*)w1B4)[o] = w1[o * 2 + 1] * ss[1];
    ((float*)fb14)[o] = fmaf(w1[o * 2 + 0], ss[2], fmaf(w1[o * 2 + 1], ss[3], b1[o]));
  }
}

// ---------------- per-row layers (scalar) ----------------
__device__ __forceinline__ void compute_h1(const float4* w1A4, const float4* w1B4,
                                           const float4* fb14, float x0, float x1,
                                           float (&h)[16]) {
#pragma unroll
  for (int q = 0; q < 4; q++) {
    float4 wa = w1A4[q], wb = w1B4[q], fb = fb14[q];
    h[4 * q + 0] = fmaxf(fmaf(wa.x, x0, fmaf(wb.x, x1, fb.x)), 0.f);
    h[4 * q + 1] = fmaxf(fmaf(wa.y, x0, fmaf(wb.y, x1, fb.y)), 0.f);
    h[4 * q + 2] = fmaxf(fmaf(wa.z, x0, fmaf(wb.z, x1, fb.z)), 0.f);
    h[4 * q + 3] = fmaxf(fmaf(wa.w, x0, fmaf(wb.w, x1, fb.w)), 0.f);
  }
}

__device__ __forceinline__ void layer16(const float4* wq, const float4* fb4,
                                        const float (&v)[16], float (&o)[16]) {
  float acc[16];
#pragma unroll
  for (int q = 0; q < 4; q++) {
    float4 b = fb4[q];
    acc[4 * q] = b.x; acc[4 * q + 1] = b.y; acc[4 * q + 2] = b.z; acc[4 * q + 3] = b.w;
  }
#pragma unroll
  for (int j = 0; j < 16; j++) {
    float vj = v[j];
#pragma unroll
    for (int q = 0; q < 4; q++) {
      float4 w = wq[j * 4 + q];
      acc[4 * q] = fmaf(w.x, vj, acc[4 * q]);
      acc[4 * q + 1] = fmaf(w.y, vj, acc[4 * q + 1]);
      acc[4 * q + 2] = fmaf(w.z, vj, acc[4 * q + 2]);
      acc[4 * q + 3] = fmaf(w.w, vj, acc[4 * q + 3]);
    }
  }
#pragma unroll
  for (int c = 0; c < 16; c++) o[c] = fmaxf(acc[c], 0.f);
}

__device__ __forceinline__ void load_h2(int row, float (&h)[16]) {
#pragma unroll
  for (int p = 0; p < 4; p++) {
    float4 f = g_h2[p * CAP + row];
    h[4 * p] = f.x; h[4 * p + 1] = f.y; h[4 * p + 2] = f.z; h[4 * p + 3] = f.w;
  }
}

__device__ __forceinline__ void stats_add(const float (&h)[16], float (&sum)[16], float (&sq)[16]) {
#pragma unroll
  for (int c = 0; c < 16; c++) {
    sum[c] += h[c];
    sq[c] = fmaf(h[c], h[c], sq[c]);
  }
}

__device__ void stats_flush(int stage, float* sAcc, float (&sum)[16], float (&sq)[16]) {
#pragma unroll
  for (int c = 0; c < 16; c++) {
    float v = sum[c], q = sq[c];
#pragma unroll
    for (int o = 16; o > 0; o >>= 1) {
      v += __shfl_xor_sync(0xffffffffu, v, o);
      q += __shfl_xor_sync(0xffffffffu, q, o);
    }
    if ((threadIdx.x & 31) == 0) {
      atomicAdd(&sAcc[c], v);
      atomicAdd(&sAcc[16 + c], q);
    }
  }
  __syncthreads();
  if (threadIdx.x < 32) atomicAdd(&g_stats[stage][threadIdx.x], sAcc[threadIdx.x]);
}

// ---------------- K0 ----------------
__global__ void k_setup(const float* __restrict__ emb, const float* __restrict__ wc,
                        const float* __restrict__ bc) {
  int t = threadIdx.x;  // 512
  if (t < 160) ((float*)g_stats)[t] = 0.f;
  int p = t >> 6, u = t & 63;
  float a = bc[u];
#pragma unroll
  for (int k = 0; k < 16; k++) a = fmaf(emb[p * 16 + k], wc[u * 32 + 16 + k], a);
  g_ctab[t] = a;
}

// ---------------- K1 ----------------
__global__ void __launch_bounds__(TB, 2) k_stats0(const float2* __restrict__ x, int n) {
  __shared__ float sAcc[4];
  if (threadIdx.x < 4) sAcc[threadIdx.x] = 0.f;
  __syncthreads();
  float s0 = 0.f, s1 = 0.f, q0 = 0.f, q1 = 0.f;
  int stride = gridDim.x * blockDim.x;
  for (int i = blockIdx.x * blockDim.x + threadIdx.x; i < n; i += stride) {
    float2 v = x[i];
    s0 += v.x; s1 += v.y;
    q0 = fmaf(v.x, v.x, q0); q1 = fmaf(v.y, v.y, q1);
  }
#pragma unroll
  for (int o = 16; o > 0; o >>= 1) {
    s0 += __shfl_xor_sync(0xffffffffu, s0, o);
    s1 += __shfl_xor_sync(0xffffffffu, s1, o);
    q0 += __shfl_xor_sync(0xffffffffu, q0, o);
    q1 += __shfl_xor_sync(0xffffffffu, q1, o);
  }
  if ((threadIdx.x & 31) == 0) {
    atomicAdd(&sAcc[0], s0); atomicAdd(&sAcc[1], s1);
    atomicAdd(&sAcc[2], q0); atomicAdd(&sAcc[3], q1);
  }
  __syncthreads();
  if (threadIdx.x < 2) {
    atomicAdd(&g_stats[0][threadIdx.x], sAcc[threadIdx.x]);
    atomicAdd(&g_stats[0][16 + threadIdx.x], sAcc[2 + threadIdx.x]);
  }
}

// ---------------- K2: h1, stats1 ----------------
__global__ void __launch_bounds__(TB, 2) k_pass2(
    const float2* __restrict__ x, int n,
    const float* __restrict__ bn0g, const float* __restrict__ bn0b,
    const float* __restrict__ w1, const float* __restrict__ b1) {
  __shared__ float ss0[4];
  __shared__ float4 w1A4[4], w1B4[4], fb14[4];
  __shared__ float sAcc[32];
  if (threadIdx.x < 32) sAcc[threadIdx.x] = 0.f;
  float invN = 1.0f / (float)n;
  fold_bn_layer1(invN, bn0g, bn0b, w1, b1, ss0, w1A4, w1B4, fb14);
  __syncthreads();

  float sum[16], sq[16];
#pragma unroll
  for (int c = 0; c < 16; c++) { sum[c] = 0.f; sq[c] = 0.f; }
  int stride = gridDim.x * blockDim.x;
  for (int i = blockIdx.x * blockDim.x + threadIdx.x; i < n; i += stride) {
    float2 xv = x[i];
    float h[16];
    compute_h1(w1A4, w1B4, fb14, xv.x, xv.y, h);
    stats_add(h, sum, sq);
  }
  stats_flush(1, sAcc, sum, sq);
}

// ---------------- K3: y1a, stats2 ----------------
__global__ void __launch_bounds__(TB, 2) k_pass3(
    const float2* __restrict__ x, int n,
    const float* __restrict__ bn0g, const float* __restrict__ bn0b,
    const float* __restrict__ bn1g, const float* __restrict__ bn1b,
    const float* __restrict__ w1, const float* __restrict__ b1,
    const float* __restrict__ w2, const float* __restrict__ b2) {
  __shared__ float ss0[4];
  __shared__ float4 w1A4[4], w1B4[4], fb14[4];
  __shared__ float ss1[32]; __shared__ float4 w2q[64], fb24[4];
  __shared__ float sAcc[32];
  if (threadIdx.x < 32) sAcc[threadIdx.x] = 0.f;
  float invN = 1.0f / (float)n;
  fold_bn_layer1(invN, bn0g, bn0b, w1, b1, ss0, w1A4, w1B4, fb14);
  fold_bn_layer16(1, invN, bn1g, bn1b, w2, b2, ss1, w2q, fb24);
  __syncthreads();

  float sum[16], sq[16];
#pragma unroll
  for (int c = 0; c < 16; c++) { sum[c] = 0.f; sq[c] = 0.f; }
  int stride = gridDim.x * blockDim.x;
  for (int i = blockIdx.x * blockDim.x + threadIdx.x; i < n; i += stride) {
    float2 xv = x[i];
    float h[16], y[16];
    compute_h1(w1A4, w1B4, fb14, xv.x, xv.y, h);
    layer16(w2q, fb24, h, y);
    stats_add(y, sum, sq);
  }
  stats_flush(2, sAcc, sum, sq);
}

// ---------------- K4: h2 = h1 + L3(BN2 y1a); store; stats3 ----------------
__global__ void __launch_bounds__(TB, 2) k_pass4(
    const float2* __restrict__ x, int n,
    const float* __restrict__ bn0g, const float* __restrict__ bn0b,
    const float* __restrict__ bn1g, const float* __restrict__ bn1b,
    const float* __restrict__ bn2g, const float* __restrict__ bn2b,
    const float* __restrict__ w1, const float* __restrict__ b1,
    const float* __restrict__ w2, const float* __restrict__ b2,
    const float* __restrict__ w3, const float* __restrict__ b3) {
  __shared__ float ss0[4];
  __shared__ float4 w1A4[4], w1B4[4], fb14[4];
  __shared__ float ss1[32]; __shared__ float4 w2q[64], fb24[4];
  __shared__ float ss2[32]; __shared__ float4 w3q[64], fb34[4];
  __shared__ float sAcc[32];
  if (threadIdx.x < 32) sAcc[threadIdx.x] = 0.f;
  float invN = 1.0f / (float)n;
  fold_bn_layer1(invN, bn0g, bn0b, w1, b1, ss0, w1A4, w1B4, fb14);
  fold_bn_layer16(1, invN, bn1g, bn1b, w2, b2, ss1, w2q, fb24);
  fold_bn_layer16(2, invN, bn2g, bn2b, w3, b3, ss2, w3q, fb34);
  __syncthreads();

  float sum[16], sq[16];
#pragma unroll
  for (int c = 0; c < 16; c++) { sum[c] = 0.f; sq[c] = 0.f; }
  int stride = gridDim.x * blockDim.x;
  for (int i = blockIdx.x * blockDim.x + threadIdx.x; i < n; i += stride) {
    float2 xv = x[i];
    float h[16], y[16], z[16];
    compute_h1(w1A4, w1B4, fb14, xv.x, xv.y, h);
    layer16(w2q, fb24, h, y);
    layer16(w3q, fb34, y, z);
#pragma unroll
    for (int c = 0; c < 16; c++) h[c] += z[c];   // h2
#pragma unroll
    for (int p = 0; p < 4; p++)
      g_h2[p * CAP + i] = make_float4(h[4 * p], h[4 * p + 1], h[4 * p + 2], h[4 * p + 3]);
    stats_add(h, sum, sq);
  }
  stats_flush(3, sAcc, sum, sq);
}

// ---------------- K5: y2a, stats4 ----------------
__global__ void __launch_bounds__(TB, 2) k_pass5(
    int n,
    const float* __restrict__ bn3g, const float* __restrict__ bn3b,
    const float* __restrict__ w4, const float* __restrict__ b4) {
  __shared__ float ss3[32]; __shared__ float4 w4q[64], fb44[4];
  __shared__ float sAcc[32];
  if (threadIdx.x < 32) sAcc[threadIdx.x] = 0.f;
  float invN = 1.0f / (float)n;
  fold_bn_layer16(3, invN, bn3g, bn3b, w4, b4, ss3, w4q, fb44);
  __syncthreads();

  float sum[16], sq[16];
#pragma unroll
  for (int c = 0; c < 16; c++) { sum[c] = 0.f; sq[c] = 0.f; }
  int stride = gridDim.x * blockDim.x;
  for (int i = blockIdx.x * blockDim.x + threadIdx.x; i < n; i += stride) {
    float h[16], y[16];
    load_h2(i, h);
    layer16(w4q, fb44, h, y);
    stats_add(y, sum, sq);
  }
  stats_flush(4, sAcc, sum, sq);
}

// ---------------- K6: final — scalar phase A, warp-coop packed phase B ----------------
__global__ void __launch_bounds__(TB, 2) k_final(
    int n, const int* __restrict__ idx, float* __restrict__ out,
    const float* __restrict__ bn3g, const float* __restrict__ bn3b,
    const float* __restrict__ bn4g, const float* __restrict__ bn4b,
    const float* __restrict__ w4, const float* __restrict__ b4,
    const float* __restrict__ w5, const float* __restrict__ b5,
    const float* __restrict__ wc) {
  __shared__ float ss3[32]; __shared__ float4 w4q[64], fb44[4];
  __shared__ float ss4[32]; __shared__ float4 w5q[64], fb54[4];
  __shared__ float2 swcp[512];        // swcp[kp*64+c] = (wc[c][2kp], wc[c][2kp+1]) head
  __shared__ float2 sct2[256];        // ctab as pairs [part*32 + cpair]
  __shared__ float2 sh3[TB * 9];      // staged h3, row stride 9 pairs (conflict-padded)
  __shared__ int spart[TB];
  float invN = 1.0f / (float)n;
  fold_bn_layer16(3, invN, bn3g, bn3b, w4, b4, ss3, w4q, fb44);
  fold_bn_layer16(4, invN, bn4g, bn4b, w5, b5, ss4, w5q, fb54);
  int t = threadIdx.x;
  int lane = t & 31, wid = t >> 5;
  {
#pragma unroll
    for (int e = t; e < 512; e += TB) {
      int kp = e >> 6, c = e & 63;
      swcp[e] = make_float2(wc[c * 32 + 2 * kp], wc[c * 32 + 2 * kp + 1]);
    }
    sct2[t] = ((const float2*)g_ctab)[t];
  }
  __syncthreads();

  int blockBase = blockIdx.x * TB;
  int i = blockBase + t;

  // phase A: per-thread row -> h3 staged to smem
  {
    float h[16], y[16], z[16];
    int part = 0;
    if (i < n) {
      load_h2(i, h);
      layer16(w4q, fb44, h, y);
      layer16(w5q, fb54, y, z);
      part = idx[i];
    } else {
#pragma unroll
      for (int c = 0; c < 16; c++) { h[c] = 0.f; z[c] = 0.f; }
    }
#pragma unroll
    for (int kp = 0; kp < 8; kp++)
      sh3[t * 9 + kp] = make_float2(h[2 * kp] + z[2 * kp], h[2 * kp + 1] + z[2 * kp + 1]);
    spart[t] = part;
  }
  __syncthreads();

  // phase B: per-lane classifier weights in registers (cols 2*lane, 2*lane+1)
  u64 wl[8], wh[8];
#pragma unroll
  for (int kp = 0; kp < 8; kp++) {
    wl[kp] = ldu64(&swcp[kp * 64 + 2 * lane]);
    wh[kp] = ldu64(&swcp[kp * 64 + 2 * lane + 1]);
  }

  int rowsLeft = n - blockBase - wid * 32;
  int rCount = rowsLeft < 32 ? (rowsLeft < 0 ? 0 : rowsLeft) : 32;
  for (int r = 0; r < rCount; r++) {
    int lrow = wid * 32 + r;
    int part = spart[lrow];                  // broadcast
    u64 hp[8];
#pragma unroll
    for (int kp = 0; kp < 8; kp++) hp[kp] = ldu64(&sh3[lrow * 9 + kp]);  // broadcast
    u64 accL = 0ull, accH = 0ull;
#pragma unroll
    for (int kp = 0; kp < 8; kp++) {
      accL = fma2(wl[kp], hp[kp], accL);
      accH = fma2(wh[kp], hp[kp], accH);
    }
    float la, lb, ha, hb, ca, cb;
    unpack2(accL, la, lb);
    unpack2(accH, ha, hb);
    unpack2(ldu64(&sct2[part * 32 + lane]), ca, cb);
    u64 res = pack2(la + lb + ca, ha + hb + cb);
    *reinterpret_cast<u64*>(out + (size_t)(blockBase + lrow) * 64 + 2 * lane) = res;
  }
}

// ---------------- launch ----------------
extern "C" void kernel_launch(void* const* d_in, const int* in_sizes, int n_in,
                              void* d_out, int out_size) {
  const float2* x  = (const float2*)d_in[0];
  const int* idx   = (const int*)d_in[1];
  const float* bn0g = (const float*)d_in[2],  *bn0b = (const float*)d_in[3];
  const float* bn1g = (const float*)d_in[4],  *bn1b = (const float*)d_in[5];
  const float* bn2g = (const float*)d_in[6],  *bn2b = (const float*)d_in[7];
  const float* bn3g = (const float*)d_in[8],  *bn3b = (const float*)d_in[9];
  const float* bn4g = (const float*)d_in[10], *bn4b = (const float*)d_in[11];
  const float* w1 = (const float*)d_in[12], *b1 = (const float*)d_in[13];
  const float* w2 = (const float*)d_in[14], *b2 = (const float*)d_in[15];
  const float* w3 = (const float*)d_in[16], *b3 = (const float*)d_in[17];
  const float* w4 = (const float*)d_in[18], *b4 = (const float*)d_in[19];
  const float* w5 = (const float*)d_in[20], *b5 = (const float*)d_in[21];
  const float* emb = (const float*)d_in[22];
  const float* wc  = (const float*)d_in[23], *bc = (const float*)d_in[24];
  float* out = (float*)d_out;
  int n = in_sizes[1];

  k_setup<<<1, 512>>>(emb, wc, bc);
  k_stats0<<<SGRID, TB>>>(x, n);
  k_pass2<<<SGRID, TB>>>(x, n, bn0g, bn0b, w1, b1);
  k_pass3<<<SGRID, TB>>>(x, n, bn0g, bn0b, bn1g, bn1b, w1, b1, w2, b2);
  k_pass4<<<SGRID, TB>>>(x, n, bn0g, bn0b, bn1g, bn1b, bn2g, bn2b, w1, b1, w2, b2, w3, b3);
  k_pass5<<<SGRID, TB>>>(n, bn3g, bn3b, w4, b4);
  k_final<<<(n + TB - 1) / TB, TB>>>(n, idx, out, bn3g, bn3b, bn4g, bn4b, w4, b4, w5, b5, wc);
}

// round 15
// speedup vs baseline: 2.6255x; 2.6255x over previous
#include <cuda_runtime.h>

typedef unsigned long long u64;
typedef unsigned int u32;

#define CAP 2097152
#define EPSBN 1e-5f
#define SGRID 1184
#define TB 256

__device__ float4 g_h2[4 * CAP];                    // h2 plane-major: [plane p][row]
__device__ float g_stats[5][32];                    // [stage][sum 0..15 | sumsq 0..15]
__device__ __align__(16) float g_ctab[8 * 64];      // emb@wc_tail^T + bc

// ---------------- packed helpers (classifier only) ----------------
__device__ __forceinline__ u64 pack2(float x, float y) {
  u64 d;
  asm("mov.b64 %0, {%1, %2};" : "=l"(d) : "r"(__float_as_uint(x)), "r"(__float_as_uint(y)));
  return d;
}
__device__ __forceinline__ void unpack2(u64 a, float& x, float& y) {
  u32 lo, hi;
  asm("mov.b64 {%0, %1}, %2;" : "=r"(lo), "=r"(hi) : "l"(a));
  x = __uint_as_float(lo); y = __uint_as_float(hi);
}
__device__ __forceinline__ u64 fma2(u64 a, u64 b, u64 c) {
  u64 d;
  asm("fma.rn.f32x2 %0, %1, %2, %3;" : "=l"(d) : "l"(a), "l"(b), "l"(c));
  return d;
}
__device__ __forceinline__ u64 ldu64(const float2* p) {
  return *reinterpret_cast<const u64*>(p);
}

// ---------------- BN fold helpers ----------------
// scale/shift for a 16-wide BN stage -> ss[0..15]=scale, ss[16..31]=shift
__device__ __forceinline__ void bn_ss16(int stage, float invN,
                                        const float* bng, const float* bnb, float* ss) {
  int t = threadIdx.x;
  if (t < 16) {
    float m = g_stats[stage][t] * invN;
    float var = fmaf(-m, m, g_stats[stage][16 + t] * invN);
    float sc = rsqrtf(var + EPSBN) * bng[t];
    ss[t] = sc;
    ss[16 + t] = bnb[t] - m * sc;
  }
}

// layer1 fold (BN0 + Linear(2,16)) into smem float4 arrays
__device__ void fold_bn_layer1(float invN,
                               const float* bng, const float* bnb,
                               const float* w1, const float* b1,
                               float* ss, float4* w1A4, float4* w1B4, float4* fb14) {
  int t = threadIdx.x;
  if (t < 2) {
    float m = g_stats[0][t] * invN;
    float var = fmaf(-m, m, g_stats[0][16 + t] * invN);
    float scale = rsqrtf(var + EPSBN) * bng[t];
    ss[t] = scale;
    ss[2 + t] = bnb[t] - m * scale;
  }
  __syncthreads();
  if (t >= 128 && t < 144) {
    int o = t - 128;
    ((float*)w1A4)[o] = w1[o * 2 + 0] * ss[0];
    ((float*)w1B4)[o] = w1[o * 2 + 1] * ss[1];
    ((float*)fb14)[o] = fmaf(w1[o * 2 + 0], ss[2], fmaf(w1[o * 2 + 1], ss[3], b1[o]));
  }
}

// per-lane folded weights for column c of a 16x16 layer
__device__ __forceinline__ void build_col_weights(const float* __restrict__ w,
                                                  const float* __restrict__ bias,
                                                  const float* ss, int c,
                                                  float (&wr)[16], float& fb) {
  fb = bias[c];
#pragma unroll
  for (int j = 0; j < 16; j++) {
    float wv = w[c * 16 + j];
    wr[j] = wv * ss[j];
    fb = fmaf(wv, ss[16 + j], fb);
  }
}

// ---------------- phase helpers ----------------
__device__ __forceinline__ void compute_h1(const float4* w1A4, const float4* w1B4,
                                           const float4* fb14, float x0, float x1,
                                           float (&h)[16]) {
#pragma unroll
  for (int q = 0; q < 4; q++) {
    float4 wa = w1A4[q], wb = w1B4[q], fb = fb14[q];
    h[4 * q + 0] = fmaxf(fmaf(wa.x, x0, fmaf(wb.x, x1, fb.x)), 0.f);
    h[4 * q + 1] = fmaxf(fmaf(wa.y, x0, fmaf(wb.y, x1, fb.y)), 0.f);
    h[4 * q + 2] = fmaxf(fmaf(wa.z, x0, fmaf(wb.z, x1, fb.z)), 0.f);
    h[4 * q + 3] = fmaxf(fmaf(wa.w, x0, fmaf(wb.w, x1, fb.w)), 0.f);
  }
}

// stage 16 floats into a stride-9-float2 row buffer
__device__ __forceinline__ void stage_row(float2* rowbuf, const float (&h)[16]) {
#pragma unroll
  for (int p = 0; p < 8; p++) rowbuf[p] = make_float2(h[2 * p], h[2 * p + 1]);
}

// y_c = relu(b'_c + sum_j W'_cj h_j), split accumulators for ILP
__device__ __forceinline__ float coop_col(const float2* rowbuf, const float (&wr)[16], float fb) {
  float a0 = fb, a1 = 0.f;
#pragma unroll
  for (int jp = 0; jp < 8; jp++) {
    float2 hp = rowbuf[jp];
    a0 = fmaf(wr[2 * jp], hp.x, a0);
    a1 = fmaf(wr[2 * jp + 1], hp.y, a1);
  }
  return fmaxf(a0 + a1, 0.f);
}

// column-stats flush (per-lane sum/sq for column c)
__device__ __forceinline__ void col_stats_flush(int stage, float* sAcc, int lane, int c,
                                                float sum, float sq) {
  sum += __shfl_xor_sync(0xffffffffu, sum, 16);
  sq += __shfl_xor_sync(0xffffffffu, sq, 16);
  if (lane < 16) {
    atomicAdd(&sAcc[c], sum);
    atomicAdd(&sAcc[16 + c], sq);
  }
  __syncthreads();
  if (threadIdx.x < 32) atomicAdd(&g_stats[stage][threadIdx.x], sAcc[threadIdx.x]);
}

// ---------------- K0 ----------------
__global__ void k_setup(const float* __restrict__ emb, const float* __restrict__ wc,
                        const float* __restrict__ bc) {
  int t = threadIdx.x;  // 512
  if (t < 160) ((float*)g_stats)[t] = 0.f;
  int p = t >> 6, u = t & 63;
  float a = bc[u];
#pragma unroll
  for (int k = 0; k < 16; k++) a = fmaf(emb[p * 16 + k], wc[u * 32 + 16 + k], a);
  g_ctab[t] = a;
}

// ---------------- K1: stats of x ----------------
__global__ void __launch_bounds__(TB) k_stats0(const float2* __restrict__ x, int n) {
  __shared__ float sAcc[4];
  if (threadIdx.x < 4) sAcc[threadIdx.x] = 0.f;
  __syncthreads();
  float s0 = 0.f, s1 = 0.f, q0 = 0.f, q1 = 0.f;
  int stride = gridDim.x * blockDim.x;
  for (int i = blockIdx.x * blockDim.x + threadIdx.x; i < n; i += stride) {
    float2 v = x[i];
    s0 += v.x; s1 += v.y;
    q0 = fmaf(v.x, v.x, q0); q1 = fmaf(v.y, v.y, q1);
  }
#pragma unroll
  for (int o = 16; o > 0; o >>= 1) {
    s0 += __shfl_xor_sync(0xffffffffu, s0, o);
    s1 += __shfl_xor_sync(0xffffffffu, s1, o);
    q0 += __shfl_xor_sync(0xffffffffu, q0, o);
    q1 += __shfl_xor_sync(0xffffffffu, q1, o);
  }
  if ((threadIdx.x & 31) == 0) {
    atomicAdd(&sAcc[0], s0); atomicAdd(&sAcc[1], s1);
    atomicAdd(&sAcc[2], q0); atomicAdd(&sAcc[3], q1);
  }
  __syncthreads();
  if (threadIdx.x < 2) {
    atomicAdd(&g_stats[0][threadIdx.x], sAcc[threadIdx.x]);
    atomicAdd(&g_stats[0][16 + threadIdx.x], sAcc[2 + threadIdx.x]);
  }
}

// ---------------- K2: h1, stats1 (warp-coop stats) ----------------
__global__ void __launch_bounds__(TB) k_pass2(
    const float2* __restrict__ x, int n,
    const float* __restrict__ bn0g, const float* __restrict__ bn0b,
    const float* __restrict__ w1, const float* __restrict__ b1) {
  __shared__ float ss0[4];
  __shared__ float4 w1A4[4], w1B4[4], fb14[4];
  __shared__ float sAcc[32];
  __shared__ float2 bufs[8][288];
  int t = threadIdx.x, lane = t & 31, wid = t >> 5;
  if (t < 32) sAcc[t] = 0.f;
  float invN = 1.0f / (float)n;
  fold_bn_layer1(invN, bn0g, bn0b, w1, b1, ss0, w1A4, w1B4, fb14);
  __syncthreads();

  int c = lane & 15, r2 = lane >> 4;
  float2* buf = bufs[wid];
  float sum = 0.f, sq = 0.f;
  int stride = gridDim.x * TB;
  for (int base = blockIdx.x * TB + wid * 32; base < n; base += stride) {
    int row = base + lane;
    float h[16];
    float2 xv = (row < n) ? x[row] : make_float2(0.f, 0.f);
    compute_h1(w1A4, w1B4, fb14, xv.x, xv.y, h);
    if (row < n) stage_row(&buf[lane * 9], h);
    __syncwarp();
    int rmax = n - base; if (rmax > 32) rmax = 32;
#pragma unroll
    for (int s = 0; s < 16; s++) {
      int r = 2 * s + r2;
      if (r < rmax) {
        float hv = ((const float*)&buf[r * 9])[c];
        sum += hv;
        sq = fmaf(hv, hv, sq);
      }
    }
    __syncwarp();
  }
  col_stats_flush(1, sAcc, lane, c, sum, sq);
}

// ---------------- K3: y1a, stats2 ----------------
__global__ void __launch_bounds__(TB) k_pass3(
    const float2* __restrict__ x, int n,
    const float* __restrict__ bn0g, const float* __restrict__ bn0b,
    const float* __restrict__ bn1g, const float* __restrict__ bn1b,
    const float* __restrict__ w1, const float* __restrict__ b1,
    const float* __restrict__ w2, const float* __restrict__ b2) {
  __shared__ float ss0[4];
  __shared__ float4 w1A4[4], w1B4[4], fb14[4];
  __shared__ float ss1[32];
  __shared__ float sAcc[32];
  __shared__ float2 bufs[8][288];
  int t = threadIdx.x, lane = t & 31, wid = t >> 5;
  if (t < 32) sAcc[t] = 0.f;
  float invN = 1.0f / (float)n;
  fold_bn_layer1(invN, bn0g, bn0b, w1, b1, ss0, w1A4, w1B4, fb14);
  bn_ss16(1, invN, bn1g, bn1b, ss1);
  __syncthreads();

  int c = lane & 15, r2 = lane >> 4;
  float wr[16], fb;
  build_col_weights(w2, b2, ss1, c, wr, fb);
  float2* buf = bufs[wid];
  float sum = 0.f, sq = 0.f;
  int stride = gridDim.x * TB;
  for (int base = blockIdx.x * TB + wid * 32; base < n; base += stride) {
    int row = base + lane;
    float h[16];
    float2 xv = (row < n) ? x[row] : make_float2(0.f, 0.f);
    compute_h1(w1A4, w1B4, fb14, xv.x, xv.y, h);
    if (row < n) stage_row(&buf[lane * 9], h);
    __syncwarp();
    int rmax = n - base; if (rmax > 32) rmax = 32;
#pragma unroll
    for (int s = 0; s < 16; s++) {
      int r = 2 * s + r2;
      if (r < rmax) {
        float y = coop_col(&buf[r * 9], wr, fb);
        sum += y;
        sq = fmaf(y, y, sq);
      }
    }
    __syncwarp();
  }
  col_stats_flush(2, sAcc, lane, c, sum, sq);
}

// ---------------- K4: h2 = h1 + L3(BN2 L2(BN1 h1)); store; stats3 ----------------
__global__ void __launch_bounds__(TB) k_pass4(
    const float2* __restrict__ x, int n,
    const float* __restrict__ bn0g, const float* __restrict__ bn0b,
    const float* __restrict__ bn1g, const float* __restrict__ bn1b,
    const float* __restrict__ bn2g, const float* __restrict__ bn2b,
    const float* __restrict__ w1, const float* __restrict__ b1,
    const float* __restrict__ w2, const float* __restrict__ b2,
    const float* __restrict__ w3, const float* __restrict__ b3) {
  __shared__ float ss0[4];
  __shared__ float4 w1A4[4], w1B4[4], fb14[4];
  __shared__ float ss1[32], ss2[32];
  __shared__ float sAcc[32];
  __shared__ float2 buf1s[8][288];
  __shared__ float2 buf2s[8][288];
  int t = threadIdx.x, lane = t & 31, wid = t >> 5;
  if (t < 32) sAcc[t] = 0.f;
  float invN = 1.0f / (float)n;
  fold_bn_layer1(invN, bn0g, bn0b, w1, b1, ss0, w1A4, w1B4, fb14);
  bn_ss16(1, invN, bn1g, bn1b, ss1);
  bn_ss16(2, invN, bn2g, bn2b, ss2);
  __syncthreads();

  int c = lane & 15, r2 = lane >> 4;
  float wrA[16], fbA, wrB[16], fbB;
  build_col_weights(w2, b2, ss1, c, wrA, fbA);
  build_col_weights(w3, b3, ss2, c, wrB, fbB);
  float2* buf1 = buf1s[wid];
  float2* buf2 = buf2s[wid];
  float sum = 0.f, sq = 0.f;
  int stride = gridDim.x * TB;
  for (int base = blockIdx.x * TB + wid * 32; base < n; base += stride) {
    int row = base + lane;
    float h[16];
    float2 xv = (row < n) ? x[row] : make_float2(0.f, 0.f);
    compute_h1(w1A4, w1B4, fb14, xv.x, xv.y, h);
    if (row < n) stage_row(&buf1[lane * 9], h);
    __syncwarp();
    int rmax = n - base; if (rmax > 32) rmax = 32;
    // B1: y = relu(W2' h1 + b2')  -> buf2
#pragma unroll
    for (int s = 0; s < 16; s++) {
      int r = 2 * s + r2;
      if (r < rmax) {
        float y = coop_col(&buf1[r * 9], wrA, fbA);
        ((float*)&buf2[r * 9])[c] = y;
      }
    }
    __syncwarp();
    // B2: z = relu(W3' y + b3'); h2 = h1 + z -> buf1 (own slot only), stats
#pragma unroll
    for (int s = 0; s < 16; s++) {
      int r = 2 * s + r2;
      if (r < rmax) {
        float z = coop_col(&buf2[r * 9], wrB, fbB);
        float h2v = ((const float*)&buf1[r * 9])[c] + z;
        ((float*)&buf1[r * 9])[c] = h2v;
        sum += h2v;
        sq = fmaf(h2v, h2v, sq);
      }
    }
    __syncwarp();
    // C: data-parallel coalesced store of h2
    if (row < n) {
      const float* hr = (const float*)&buf1[lane * 9];
#pragma unroll
      for (int p = 0; p < 4; p++)
        g_h2[p * CAP + row] = make_float4(hr[4 * p], hr[4 * p + 1], hr[4 * p + 2], hr[4 * p + 3]);
    }
    __syncwarp();
  }
  col_stats_flush(3, sAcc, lane, c, sum, sq);
}

// ---------------- K5: y2a, stats4 ----------------
__global__ void __launch_bounds__(TB) k_pass5(
    int n,
    const float* __restrict__ bn3g, const float* __restrict__ bn3b,
    const float* __restrict__ w4, const float* __restrict__ b4) {
  __shared__ float ss3[32];
  __shared__ float sAcc[32];
  __shared__ float2 bufs[8][288];
  int t = threadIdx.x, lane = t & 31, wid = t >> 5;
  if (t < 32) sAcc[t] = 0.f;
  float invN = 1.0f / (float)n;
  bn_ss16(3, invN, bn3g, bn3b, ss3);
  __syncthreads();

  int c = lane & 15, r2 = lane >> 4;
  float wr[16], fb;
  build_col_weights(w4, b4, ss3, c, wr, fb);
  float2* buf = bufs[wid];
  float sum = 0.f, sq = 0.f;
  int stride = gridDim.x * TB;
  for (int base = blockIdx.x * TB + wid * 32; base < n; base += stride) {
    int row = base + lane;
    if (row < n) {
      float h[16];
#pragma unroll
      for (int p = 0; p < 4; p++) {
        float4 f = g_h2[p * CAP + row];
        h[4 * p] = f.x; h[4 * p + 1] = f.y; h[4 * p + 2] = f.z; h[4 * p + 3] = f.w;
      }
      stage_row(&buf[lane * 9], h);
    }
    __syncwarp();
    int rmax = n - base; if (rmax > 32) rmax = 32;
#pragma unroll
    for (int s = 0; s < 16; s++) {
      int r = 2 * s + r2;
      if (r < rmax) {
        float y = coop_col(&buf[r * 9], wr, fb);
        sum += y;
        sq = fmaf(y, y, sq);
      }
    }
    __syncwarp();
  }
  col_stats_flush(4, sAcc, lane, c, sum, sq);
}

// ---------------- K6: final ----------------
__global__ void __launch_bounds__(TB) k_final(
    int n, const int* __restrict__ idx, float* __restrict__ out,
    const float* __restrict__ bn3g, const float* __restrict__ bn3b,
    const float* __restrict__ bn4g, const float* __restrict__ bn4b,
    const float* __restrict__ w4, const float* __restrict__ b4,
    const float* __restrict__ w5, const float* __restrict__ b5,
    const float* __restrict__ wc) {
  __shared__ float ss3[32], ss4[32];
  __shared__ float2 sct2[256];
  __shared__ float2 buf1s[8][288];
  __shared__ float2 buf2s[8][288];
  __shared__ int spart[8][32];
  int t = threadIdx.x, lane = t & 31, wid = t >> 5;
  float invN = 1.0f / (float)n;
  bn_ss16(3, invN, bn3g, bn3b, ss3);
  bn_ss16(4, invN, bn4g, bn4b, ss4);
  sct2[t] = ((const float2*)g_ctab)[t];
  __syncthreads();

  int c = lane & 15, r2 = lane >> 4;
  float wrA[16], fbA, wrB[16], fbB;
  build_col_weights(w4, b4, ss3, c, wrA, fbA);
  build_col_weights(w5, b5, ss4, c, wrB, fbB);
  // classifier weights: lane owns output cols 2*lane, 2*lane+1 (head part of wc)
  u64 wl[8], wh[8];
#pragma unroll
  for (int kp = 0; kp < 8; kp++) {
    wl[kp] = ldu64((const float2*)&wc[(2 * lane) * 32 + 2 * kp]);
    wh[kp] = ldu64((const float2*)&wc[(2 * lane + 1) * 32 + 2 * kp]);
  }

  float2* buf1 = buf1s[wid];
  float2* buf2 = buf2s[wid];
  int base = blockIdx.x * TB + wid * 32;
  int row = base + lane;

  // phase A: load h2, stage; also part index
  if (row < n) {
    float h[16];
#pragma unroll
    for (int p = 0; p < 4; p++) {
      float4 f = g_h2[p * CAP + row];
      h[4 * p] = f.x; h[4 * p + 1] = f.y; h[4 * p + 2] = f.z; h[4 * p + 3] = f.w;
    }
    stage_row(&buf1[lane * 9], h);
    spart[wid][lane] = idx[row];
  }
  __syncwarp();
  int rmax = n - base; if (rmax > 32) rmax = 32; if (rmax < 0) rmax = 0;

  // B1: y = relu(W4' h2 + b4') -> buf2
#pragma unroll
  for (int s = 0; s < 16; s++) {
    int r = 2 * s + r2;
    if (r < rmax) {
      float y = coop_col(&buf1[r * 9], wrA, fbA);
      ((float*)&buf2[r * 9])[c] = y;
    }
  }
  __syncwarp();
  // B2: z = relu(W5' y + b5'); h3 = h2 + z -> buf1 (own slot)
#pragma unroll
  for (int s = 0; s < 16; s++) {
    int r = 2 * s + r2;
    if (r < rmax) {
      float z = coop_col(&buf2[r * 9], wrB, fbB);
      float h3v = ((const float*)&buf1[r * 9])[c] + z;
      ((float*)&buf1[r * 9])[c] = h3v;
    }
  }
  __syncwarp();

  // phase C: warp-coop classifier; per row: 8 broadcast pair loads + 16 fma2/lane
  for (int r = 0; r < rmax; r++) {
    int part = spart[wid][r];
    u64 hp[8];
#pragma unroll
    for (int kp = 0; kp < 8; kp++) hp[kp] = ldu64(&buf1[r * 9 + kp]);
    u64 accL = 0ull, accH = 0ull;
#pragma unroll
    for (int kp = 0; kp < 8; kp++) {
      accL = fma2(wl[kp], hp[kp], accL);
      accH = fma2(wh[kp], hp[kp], accH);
    }
    float la, lb, ha, hb, ca, cb;
    unpack2(accL, la, lb);
    unpack2(accH, ha, hb);
    unpack2(ldu64(&sct2[part * 32 + lane]), ca, cb);
    u64 res = pack2(la + lb + ca, ha + hb + cb);
    *reinterpret_cast<u64*>(out + (size_t)(base + r) * 64 + 2 * lane) = res;
  }
}

// ---------------- launch ----------------
extern "C" void kernel_launch(void* const* d_in, const int* in_sizes, int n_in,
                              void* d_out, int out_size) {
  const float2* x  = (const float2*)d_in[0];
  const int* idx   = (const int*)d_in[1];
  const float* bn0g = (const float*)d_in[2],  *bn0b = (const float*)d_in[3];
  const float* bn1g = (const float*)d_in[4],  *bn1b = (const float*)d_in[5];
  const float* bn2g = (const float*)d_in[6],  *bn2b = (const float*)d_in[7];
  const float* bn3g = (const float*)d_in[8],  *bn3b = (const float*)d_in[9];
  const float* bn4g = (const float*)d_in[10], *bn4b = (const float*)d_in[11];
  const float* w1 = (const float*)d_in[12], *b1 = (const float*)d_in[13];
  const float* w2 = (const float*)d_in[14], *b2 = (const float*)d_in[15];
  const float* w3 = (const float*)d_in[16], *b3 = (const float*)d_in[17];
  const float* w4 = (const float*)d_in[18], *b4 = (const float*)d_in[19];
  const float* w5 = (const float*)d_in[20], *b5 = (const float*)d_in[21];
  const float* emb = (const float*)d_in[22];
  const float* wc  = (const float*)d_in[23], *bc = (const float*)d_in[24];
  float* out = (float*)d_out;
  int n = in_sizes[1];

  k_setup<<<1, 512>>>(emb, wc, bc);
  k_stats0<<<SGRID, TB>>>(x, n);
  k_pass2<<<SGRID, TB>>>(x, n, bn0g, bn0b, w1, b1);
  k_pass3<<<SGRID, TB>>>(x, n, bn0g, bn0b, bn1g, bn1b, w1, b1, w2, b2);
  k_pass4<<<SGRID, TB>>>(x, n, bn0g, bn0b, bn1g, bn1b, bn2g, bn2b, w1, b1, w2, b2, w3, b3);
  k_pass5<<<SGRID, TB>>>(n, bn3g, bn3b, w4, b4);
  k_final<<<(n + TB - 1) / TB, TB>>>(n, idx, out, bn3g, bn3b, bn4g, bn4b, w4, b4, w5, b5, wc);
}

// round 16
// speedup vs baseline: 3.5248x; 1.3425x over previous
#include <cuda_runtime.h>

typedef unsigned long long u64;
typedef unsigned int u32;

#define CAP 2097152
#define EPSBN 1e-5f
#define SGRID 1184
#define TB 256
#define RS 5   // smem row stride in float4 units (80B, conflict-stagger)

__device__ float4 g_h2[4 * CAP];                    // h2 plane-major: [plane p][row]
__device__ float g_stats[5][32];                    // [stage][sum 0..15 | sumsq 0..15]
__device__ __align__(16) float g_ctab[8 * 64];      // emb@wc_tail^T + bc

// ---------------- packed helpers (classifier only) ----------------
__device__ __forceinline__ u64 pack2(float x, float y) {
  u64 d;
  asm("mov.b64 %0, {%1, %2};" : "=l"(d) : "r"(__float_as_uint(x)), "r"(__float_as_uint(y)));
  return d;
}
__device__ __forceinline__ void unpack2(u64 a, float& x, float& y) {
  u32 lo, hi;
  asm("mov.b64 {%0, %1}, %2;" : "=r"(lo), "=r"(hi) : "l"(a));
  x = __uint_as_float(lo); y = __uint_as_float(hi);
}
__device__ __forceinline__ u64 fma2(u64 a, u64 b, u64 c) {
  u64 d;
  asm("fma.rn.f32x2 %0, %1, %2, %3;" : "=l"(d) : "l"(a), "l"(b), "l"(c));
  return d;
}
__device__ __forceinline__ u64 ldu64(const float2* p) {
  return *reinterpret_cast<const u64*>(p);
}

// ---------------- BN fold helpers ----------------
__device__ __forceinline__ void bn_ss16(int stage, float invN,
                                        const float* bng, const float* bnb, float* ss) {
  int t = threadIdx.x;
  if (t < 16) {
    float m = g_stats[stage][t] * invN;
    float var = fmaf(-m, m, g_stats[stage][16 + t] * invN);
    float sc = rsqrtf(var + EPSBN) * bng[t];
    ss[t] = sc;
    ss[16 + t] = bnb[t] - m * sc;
  }
}

__device__ void fold_bn_layer1(float invN,
                               const float* bng, const float* bnb,
                               const float* w1, const float* b1,
                               float* ss, float4* w1A4, float4* w1B4, float4* fb14) {
  int t = threadIdx.x;
  if (t < 2) {
    float m = g_stats[0][t] * invN;
    float var = fmaf(-m, m, g_stats[0][16 + t] * invN);
    float scale = rsqrtf(var + EPSBN) * bng[t];
    ss[t] = scale;
    ss[2 + t] = bnb[t] - m * scale;
  }
  __syncthreads();
  if (t >= 128 && t < 144) {
    int o = t - 128;
    ((float*)w1A4)[o] = w1[o * 2 + 0] * ss[0];
    ((float*)w1B4)[o] = w1[o * 2 + 1] * ss[1];
    ((float*)fb14)[o] = fmaf(w1[o * 2 + 0], ss[2], fmaf(w1[o * 2 + 1], ss[3], b1[o]));
  }
}

__device__ __forceinline__ void build_col_weights(const float* __restrict__ w,
                                                  const float* __restrict__ bias,
                                                  const float* ss, int c,
                                                  float (&wr)[16], float& fb) {
  fb = bias[c];
#pragma unroll
  for (int j = 0; j < 16; j++) {
    float wv = w[c * 16 + j];
    wr[j] = wv * ss[j];
    fb = fmaf(wv, ss[16 + j], fb);
  }
}

// ---------------- phase helpers ----------------
__device__ __forceinline__ void compute_h1(const float4* w1A4, const float4* w1B4,
                                           const float4* fb14, float x0, float x1,
                                           float (&h)[16]) {
#pragma unroll
  for (int q = 0; q < 4; q++) {
    float4 wa = w1A4[q], wb = w1B4[q], fb = fb14[q];
    h[4 * q + 0] = fmaxf(fmaf(wa.x, x0, fmaf(wb.x, x1, fb.x)), 0.f);
    h[4 * q + 1] = fmaxf(fmaf(wa.y, x0, fmaf(wb.y, x1, fb.y)), 0.f);
    h[4 * q + 2] = fmaxf(fmaf(wa.z, x0, fmaf(wb.z, x1, fb.z)), 0.f);
    h[4 * q + 3] = fmaxf(fmaf(wa.w, x0, fmaf(wb.w, x1, fb.w)), 0.f);
  }
}

__device__ __forceinline__ void stage_row4(float4* rowbuf, const float (&h)[16]) {
#pragma unroll
  for (int q = 0; q < 4; q++)
    rowbuf[q] = make_float4(h[4 * q], h[4 * q + 1], h[4 * q + 2], h[4 * q + 3]);
}

// y_c = relu(b'_c + sum_j W'_cj h_j); 4x LDS.128, 4 accumulators
__device__ __forceinline__ float coop_col4(const float4* rowbuf, const float (&wr)[16], float fb) {
  float a0 = fb, a1 = 0.f, a2 = 0.f, a3 = 0.f;
#pragma unroll
  for (int q = 0; q < 4; q++) {
    float4 hv = rowbuf[q];
    a0 = fmaf(wr[4 * q + 0], hv.x, a0);
    a1 = fmaf(wr[4 * q + 1], hv.y, a1);
    a2 = fmaf(wr[4 * q + 2], hv.z, a2);
    a3 = fmaf(wr[4 * q + 3], hv.w, a3);
  }
  return fmaxf((a0 + a1) + (a2 + a3), 0.f);
}

__device__ __forceinline__ void col_stats_flush(int stage, float* sAcc, int lane, int c,
                                                float sum, float sq) {
  sum += __shfl_xor_sync(0xffffffffu, sum, 16);
  sq += __shfl_xor_sync(0xffffffffu, sq, 16);
  if (lane < 16) {
    atomicAdd(&sAcc[c], sum);
    atomicAdd(&sAcc[16 + c], sq);
  }
  __syncthreads();
  if (threadIdx.x < 32) atomicAdd(&g_stats[stage][threadIdx.x], sAcc[threadIdx.x]);
}

// ---------------- K0 ----------------
__global__ void k_setup(const float* __restrict__ emb, const float* __restrict__ wc,
                        const float* __restrict__ bc) {
  int t = threadIdx.x;  // 512
  if (t < 160) ((float*)g_stats)[t] = 0.f;
  int p = t >> 6, u = t & 63;
  float a = bc[u];
#pragma unroll
  for (int k = 0; k < 16; k++) a = fmaf(emb[p * 16 + k], wc[u * 32 + 16 + k], a);
  g_ctab[t] = a;
}

// ---------------- K1: stats of x ----------------
__global__ void __launch_bounds__(TB) k_stats0(const float2* __restrict__ x, int n) {
  __shared__ float sAcc[4];
  if (threadIdx.x < 4) sAcc[threadIdx.x] = 0.f;
  __syncthreads();
  float s0 = 0.f, s1 = 0.f, q0 = 0.f, q1 = 0.f;
  int stride = gridDim.x * blockDim.x;
  for (int i = blockIdx.x * blockDim.x + threadIdx.x; i < n; i += stride) {
    float2 v = x[i];
    s0 += v.x; s1 += v.y;
    q0 = fmaf(v.x, v.x, q0); q1 = fmaf(v.y, v.y, q1);
  }
#pragma unroll
  for (int o = 16; o > 0; o >>= 1) {
    s0 += __shfl_xor_sync(0xffffffffu, s0, o);
    s1 += __shfl_xor_sync(0xffffffffu, s1, o);
    q0 += __shfl_xor_sync(0xffffffffu, q0, o);
    q1 += __shfl_xor_sync(0xffffffffu, q1, o);
  }
  if ((threadIdx.x & 31) == 0) {
    atomicAdd(&sAcc[0], s0); atomicAdd(&sAcc[1], s1);
    atomicAdd(&sAcc[2], q0); atomicAdd(&sAcc[3], q1);
  }
  __syncthreads();
  if (threadIdx.x < 2) {
    atomicAdd(&g_stats[0][threadIdx.x], sAcc[threadIdx.x]);
    atomicAdd(&g_stats[0][16 + threadIdx.x], sAcc[2 + threadIdx.x]);
  }
}

// ---------------- K2: h1, stats1 ----------------
__global__ void __launch_bounds__(TB) k_pass2(
    const float2* __restrict__ x, int n,
    const float* __restrict__ bn0g, const float* __restrict__ bn0b,
    const float* __restrict__ w1, const float* __restrict__ b1) {
  __shared__ float ss0[4];
  __shared__ float4 w1A4[4], w1B4[4], fb14[4];
  __shared__ float sAcc[32];
  __shared__ float4 bufs[8][32 * RS];
  int t = threadIdx.x, lane = t & 31, wid = t >> 5;
  if (t < 32) sAcc[t] = 0.f;
  float invN = 1.0f / (float)n;
  fold_bn_layer1(invN, bn0g, bn0b, w1, b1, ss0, w1A4, w1B4, fb14);
  __syncthreads();

  int c = lane & 15, r2 = lane >> 4;
  float4* buf = bufs[wid];
  float sum = 0.f, sq = 0.f;
  int stride = gridDim.x * TB;
  for (int base = blockIdx.x * TB + wid * 32; base < n; base += stride) {
    int row = base + lane;
    int rmax = n - base; if (rmax > 32) rmax = 32;
    float h[16];
    float2 xv = (row < n) ? x[row] : make_float2(0.f, 0.f);
    compute_h1(w1A4, w1B4, fb14, xv.x, xv.y, h);
    if (row < n) stage_row4(&buf[lane * RS], h);
    __syncwarp();
    if (rmax == 32) {
#pragma unroll
      for (int s = 0; s < 16; s++) {
        int r = 2 * s + r2;
        float hv = ((const float*)&buf[r * RS])[c];
        sum += hv;
        sq = fmaf(hv, hv, sq);
      }
    } else {
#pragma unroll
      for (int s = 0; s < 16; s++) {
        int r = 2 * s + r2;
        if (r < rmax) {
          float hv = ((const float*)&buf[r * RS])[c];
          sum += hv;
          sq = fmaf(hv, hv, sq);
        }
      }
    }
    __syncwarp();
  }
  col_stats_flush(1, sAcc, lane, c, sum, sq);
}

// ---------------- K3: y1a, stats2 ----------------
__global__ void __launch_bounds__(TB) k_pass3(
    const float2* __restrict__ x, int n,
    const float* __restrict__ bn0g, const float* __restrict__ bn0b,
    const float* __restrict__ bn1g, const float* __restrict__ bn1b,
    const float* __restrict__ w1, const float* __restrict__ b1,
    const float* __restrict__ w2, const float* __restrict__ b2) {
  __shared__ float ss0[4];
  __shared__ float4 w1A4[4], w1B4[4], fb14[4];
  __shared__ float ss1[32];
  __shared__ float sAcc[32];
  __shared__ float4 bufs[8][32 * RS];
  int t = threadIdx.x, lane = t & 31, wid = t >> 5;
  if (t < 32) sAcc[t] = 0.f;
  float invN = 1.0f / (float)n;
  fold_bn_layer1(invN, bn0g, bn0b, w1, b1, ss0, w1A4, w1B4, fb14);
  bn_ss16(1, invN, bn1g, bn1b, ss1);
  __syncthreads();

  int c = lane & 15, r2 = lane >> 4;
  float wr[16], fb;
  build_col_weights(w2, b2, ss1, c, wr, fb);
  float4* buf = bufs[wid];
  float sum = 0.f, sq = 0.f;
  int stride = gridDim.x * TB;
  for (int base = blockIdx.x * TB + wid * 32; base < n; base += stride) {
    int row = base + lane;
    int rmax = n - base; if (rmax > 32) rmax = 32;
    float h[16];
    float2 xv = (row < n) ? x[row] : make_float2(0.f, 0.f);
    compute_h1(w1A4, w1B4, fb14, xv.x, xv.y, h);
    if (row < n) stage_row4(&buf[lane * RS], h);
    __syncwarp();
    if (rmax == 32) {
#pragma unroll
      for (int s = 0; s < 16; s++) {
        int r = 2 * s + r2;
        float y = coop_col4(&buf[r * RS], wr, fb);
        sum += y;
        sq = fmaf(y, y, sq);
      }
    } else {
#pragma unroll
      for (int s = 0; s < 16; s++) {
        int r = 2 * s + r2;
        if (r < rmax) {
          float y = coop_col4(&buf[r * RS], wr, fb);
          sum += y;
          sq = fmaf(y, y, sq);
        }
      }
    }
    __syncwarp();
  }
  col_stats_flush(2, sAcc, lane, c, sum, sq);
}

// ---------------- K4: h2 = h1 + L3(BN2 L2(BN1 h1)); store; stats3 ----------------
__global__ void __launch_bounds__(TB) k_pass4(
    const float2* __restrict__ x, int n,
    const float* __restrict__ bn0g, const float* __restrict__ bn0b,
    const float* __restrict__ bn1g, const float* __restrict__ bn1b,
    const float* __restrict__ bn2g, const float* __restrict__ bn2b,
    const float* __restrict__ w1, const float* __restrict__ b1,
    const float* __restrict__ w2, const float* __restrict__ b2,
    const float* __restrict__ w3, const float* __restrict__ b3) {
  __shared__ float ss0[4];
  __shared__ float4 w1A4[4], w1B4[4], fb14[4];
  __shared__ float ss1[32], ss2[32];
  __shared__ float sAcc[32];
  __shared__ float4 buf1s[8][32 * RS];
  __shared__ float4 buf2s[8][32 * RS];
  int t = threadIdx.x, lane = t & 31, wid = t >> 5;
  if (t < 32) sAcc[t] = 0.f;
  float invN = 1.0f / (float)n;
  fold_bn_layer1(invN, bn0g, bn0b, w1, b1, ss0, w1A4, w1B4, fb14);
  bn_ss16(1, invN, bn1g, bn1b, ss1);
  bn_ss16(2, invN, bn2g, bn2b, ss2);
  __syncthreads();

  int c = lane & 15, r2 = lane >> 4;
  float wrA[16], fbA, wrB[16], fbB;
  build_col_weights(w2, b2, ss1, c, wrA, fbA);
  build_col_weights(w3, b3, ss2, c, wrB, fbB);
  float4* buf1 = buf1s[wid];
  float4* buf2 = buf2s[wid];
  float sum = 0.f, sq = 0.f;
  int stride = gridDim.x * TB;
  for (int base = blockIdx.x * TB + wid * 32; base < n; base += stride) {
    int row = base + lane;
    int rmax = n - base; if (rmax > 32) rmax = 32;
    float h[16];
    float2 xv = (row < n) ? x[row] : make_float2(0.f, 0.f);
    compute_h1(w1A4, w1B4, fb14, xv.x, xv.y, h);
    if (row < n) stage_row4(&buf1[lane * RS], h);
    __syncwarp();
    if (rmax == 32) {
#pragma unroll
      for (int s = 0; s < 16; s++) {
        int r = 2 * s + r2;
        ((float*)&buf2[r * RS])[c] = coop_col4(&buf1[r * RS], wrA, fbA);
      }
      __syncwarp();
#pragma unroll
      for (int s = 0; s < 16; s++) {
        int r = 2 * s + r2;
        float z = coop_col4(&buf2[r * RS], wrB, fbB);
        float h2v = ((const float*)&buf1[r * RS])[c] + z;
        ((float*)&buf1[r * RS])[c] = h2v;
        sum += h2v;
        sq = fmaf(h2v, h2v, sq);
      }
    } else {
#pragma unroll
      for (int s = 0; s < 16; s++) {
        int r = 2 * s + r2;
        if (r < rmax)
          ((float*)&buf2[r * RS])[c] = coop_col4(&buf1[r * RS], wrA, fbA);
      }
      __syncwarp();
#pragma unroll
      for (int s = 0; s < 16; s++) {
        int r = 2 * s + r2;
        if (r < rmax) {
          float z = coop_col4(&buf2[r * RS], wrB, fbB);
          float h2v = ((const float*)&buf1[r * RS])[c] + z;
          ((float*)&buf1[r * RS])[c] = h2v;
          sum += h2v;
          sq = fmaf(h2v, h2v, sq);
        }
      }
    }
    __syncwarp();
    if (row < n) {
      const float4* hr = &buf1[lane * RS];
#pragma unroll
      for (int p = 0; p < 4; p++) g_h2[p * CAP + row] = hr[p];
    }
    __syncwarp();
  }
  col_stats_flush(3, sAcc, lane, c, sum, sq);
}

// ---------------- K5: y2a, stats4 ----------------
__global__ void __launch_bounds__(TB) k_pass5(
    int n,
    const float* __restrict__ bn3g, const float* __restrict__ bn3b,
    const float* __restrict__ w4, const float* __restrict__ b4) {
  __shared__ float ss3[32];
  __shared__ float sAcc[32];
  __shared__ float4 bufs[8][32 * RS];
  int t = threadIdx.x, lane = t & 31, wid = t >> 5;
  if (t < 32) sAcc[t] = 0.f;
  float invN = 1.0f / (float)n;
  bn_ss16(3, invN, bn3g, bn3b, ss3);
  __syncthreads();

  int c = lane & 15, r2 = lane >> 4;
  float wr[16], fb;
  build_col_weights(w4, b4, ss3, c, wr, fb);
  float4* buf = bufs[wid];
  float sum = 0.f, sq = 0.f;
  int stride = gridDim.x * TB;
  for (int base = blockIdx.x * TB + wid * 32; base < n; base += stride) {
    int row = base + lane;
    int rmax = n - base; if (rmax > 32) rmax = 32;
    if (row < n) {
#pragma unroll
      for (int p = 0; p < 4; p++) buf[lane * RS + p] = g_h2[p * CAP + row];
    }
    __syncwarp();
    if (rmax == 32) {
#pragma unroll
      for (int s = 0; s < 16; s++) {
        int r = 2 * s + r2;
        float y = coop_col4(&buf[r * RS], wr, fb);
        sum += y;
        sq = fmaf(y, y, sq);
      }
    } else {
#pragma unroll
      for (int s = 0; s < 16; s++) {
        int r = 2 * s + r2;
        if (r < rmax) {
          float y = coop_col4(&buf[r * RS], wr, fb);
          sum += y;
          sq = fmaf(y, y, sq);
        }
      }
    }
    __syncwarp();
  }
  col_stats_flush(4, sAcc, lane, c, sum, sq);
}

// ---------------- K6: final (persistent grid-stride) ----------------
__global__ void __launch_bounds__(TB) k_final(
    int n, const int* __restrict__ idx, float* __restrict__ out,
    const float* __restrict__ bn3g, const float* __restrict__ bn3b,
    const float* __restrict__ bn4g, const float* __restrict__ bn4b,
    const float* __restrict__ w4, const float* __restrict__ b4,
    const float* __restrict__ w5, const float* __restrict__ b5,
    const float* __restrict__ wc) {
  __shared__ float ss3[32], ss4[32];
  __shared__ float2 sct2[256];
  __shared__ float4 buf1s[8][32 * RS];
  __shared__ float4 buf2s[8][32 * RS];
  __shared__ int spart[8][32];
  int t = threadIdx.x, lane = t & 31, wid = t >> 5;
  float invN = 1.0f / (float)n;
  bn_ss16(3, invN, bn3g, bn3b, ss3);
  bn_ss16(4, invN, bn4g, bn4b, ss4);
  sct2[t] = ((const float2*)g_ctab)[t];
  __syncthreads();

  int c = lane & 15, r2 = lane >> 4;
  float wrA[16], fbA, wrB[16], fbB;
  build_col_weights(w4, b4, ss3, c, wrA, fbA);
  build_col_weights(w5, b5, ss4, c, wrB, fbB);
  u64 wl[8], wh[8];
#pragma unroll
  for (int kp = 0; kp < 8; kp++) {
    wl[kp] = ldu64((const float2*)&wc[(2 * lane) * 32 + 2 * kp]);
    wh[kp] = ldu64((const float2*)&wc[(2 * lane + 1) * 32 + 2 * kp]);
  }

  float4* buf1 = buf1s[wid];
  float4* buf2 = buf2s[wid];
  int stride = gridDim.x * TB;
  for (int base = blockIdx.x * TB + wid * 32; base < n; base += stride) {
    int row = base + lane;
    int rmax = n - base; if (rmax > 32) rmax = 32;
    // phase A: load h2 tile + part indices
    if (row < n) {
#pragma unroll
      for (int p = 0; p < 4; p++) buf1[lane * RS + p] = g_h2[p * CAP + row];
      spart[wid][lane] = idx[row];
    }
    __syncwarp();
    // phase B: y = relu(W4' h2); h3 = h2 + relu(W5' y)
    if (rmax == 32) {
#pragma unroll
      for (int s = 0; s < 16; s++) {
        int r = 2 * s + r2;
        ((float*)&buf2[r * RS])[c] = coop_col4(&buf1[r * RS], wrA, fbA);
      }
      __syncwarp();
#pragma unroll
      for (int s = 0; s < 16; s++) {
        int r = 2 * s + r2;
        float z = coop_col4(&buf2[r * RS], wrB, fbB);
        ((float*)&buf1[r * RS])[c] = ((const float*)&buf1[r * RS])[c] + z;
      }
    } else {
#pragma unroll
      for (int s = 0; s < 16; s++) {
        int r = 2 * s + r2;
        if (r < rmax)
          ((float*)&buf2[r * RS])[c] = coop_col4(&buf1[r * RS], wrA, fbA);
      }
      __syncwarp();
#pragma unroll
      for (int s = 0; s < 16; s++) {
        int r = 2 * s + r2;
        if (r < rmax) {
          float z = coop_col4(&buf2[r * RS], wrB, fbB);
          ((float*)&buf1[r * RS])[c] = ((const float*)&buf1[r * RS])[c] + z;
        }
      }
    }
    __syncwarp();
    // phase C: warp-coop classifier, coalesced 256B row writes
    for (int r = 0; r < rmax; r++) {
      int part = spart[wid][r];
      const float4* rb = &buf1[r * RS];
      ulonglong2 h01 = *reinterpret_cast<const ulonglong2*>(rb + 0);
      ulonglong2 h23 = *reinterpret_cast<const ulonglong2*>(rb + 1);
      ulonglong2 h45 = *reinterpret_cast<const ulonglong2*>(rb + 2);
      ulonglong2 h67 = *reinterpret_cast<const ulonglong2*>(rb + 3);
      u64 accL = 0ull, accH = 0ull;
      accL = fma2(wl[0], h01.x, accL); accH = fma2(wh[0], h01.x, accH);
      accL = fma2(wl[1], h01.y, accL); accH = fma2(wh[1], h01.y, accH);
      accL = fma2(wl[2], h23.x, accL); accH = fma2(wh[2], h23.x, accH);
      accL = fma2(wl[3], h23.y, accL); accH = fma2(wh[3], h23.y, accH);
      accL = fma2(wl[4], h45.x, accL); accH = fma2(wh[4], h45.x, accH);
      accL = fma2(wl[5], h45.y, accL); accH = fma2(wh[5], h45.y, accH);
      accL = fma2(wl[6], h67.x, accL); accH = fma2(wh[6], h67.x, accH);
      accL = fma2(wl[7], h67.y, accL); accH = fma2(wh[7], h67.y, accH);
      float la, lb, ha, hb, ca, cb;
      unpack2(accL, la, lb);
      unpack2(accH, ha, hb);
      unpack2(ldu64(&sct2[part * 32 + lane]), ca, cb);
      u64 res = pack2(la + lb + ca, ha + hb + cb);
      *reinterpret_cast<u64*>(out + (size_t)(base + r) * 64 + 2 * lane) = res;
    }
    __syncwarp();
  }
}

// ---------------- launch ----------------
extern "C" void kernel_launch(void* const* d_in, const int* in_sizes, int n_in,
                              void* d_out, int out_size) {
  const float2* x  = (const float2*)d_in[0];
  const int* idx   = (const int*)d_in[1];
  const float* bn0g = (const float*)d_in[2],  *bn0b = (const float*)d_in[3];
  const float* bn1g = (const float*)d_in[4],  *bn1b = (const float*)d_in[5];
  const float* bn2g = (const float*)d_in[6],  *bn2b = (const float*)d_in[7];
  const float* bn3g = (const float*)d_in[8],  *bn3b = (const float*)d_in[9];
  const float* bn4g = (const float*)d_in[10], *bn4b = (const float*)d_in[11];
  const float* w1 = (const float*)d_in[12], *b1 = (const float*)d_in[13];
  const float* w2 = (const float*)d_in[14], *b2 = (const float*)d_in[15];
  const float* w3 = (const float*)d_in[16], *b3 = (const float*)d_in[17];
  const float* w4 = (const float*)d_in[18], *b4 = (const float*)d_in[19];
  const float* w5 = (const float*)d_in[20], *b5 = (const float*)d_in[21];
  const float* emb = (const float*)d_in[22];
  const float* wc  = (const float*)d_in[23], *bc = (const float*)d_in[24];
  float* out = (float*)d_out;
  int n = in_sizes[1];

  k_setup<<<1, 512>>>(emb, wc, bc);
  k_stats0<<<SGRID, TB>>>(x, n);
  k_pass2<<<SGRID, TB>>>(x, n, bn0g, bn0b, w1, b1);
  k_pass3<<<SGRID, TB>>>(x, n, bn0g, bn0b, bn1g, bn1b, w1, b1, w2, b2);
  k_pass4<<<SGRID, TB>>>(x, n, bn0g, bn0b, bn1g, bn1b, bn2g, bn2b, w1, b1, w2, b2, w3, b3);
  k_pass5<<<SGRID, TB>>>(n, bn3g, bn3b, w4, b4);
  k_final<<<SGRID, TB>>>(n, idx, out, bn3g, bn3b, bn4g, bn4b, w4, b4, w5, b5, wc);
}